// round 11
// baseline (speedup 1.0000x reference)
#include <cuda_runtime.h>
#include <cstdint>

#define NFIELDS 32
#define EMBED   64
#define NPAIRS  496
#define BATCH   2048
#define EMB_ROW (NFIELDS * EMBED)   // 2048 floats per batch
#define KER_ROW (NPAIRS * EMBED)    // 31744 floats per i row

#define BM      128                 // batches per block
#define PCHUNK  8                   // pairs per block (all share one r)
#define NCHUNKS 76                  // sum over r of ceil((31-r)/8)
#define NTHREADS 256

#define ASTR 68                     // raw A row stride (floats)
#define BSTR 68                     // raw B row stride
#define A_FLOATS (BM * ASTR)        // 8704
#define B_FLOATS (EMBED * BSTR)     // 4352

__device__ __forceinline__ uint32_t f2tf32(float x) {
    uint32_t r;
    asm("cvt.rna.tf32.f32 %0, %1;" : "=r"(r) : "f"(x));
    return r;
}

__device__ __forceinline__ void mma_tf32(float* d, uint32_t a0, uint32_t a1,
                                         uint32_t a2, uint32_t a3,
                                         uint32_t b0, uint32_t b1) {
    asm("mma.sync.aligned.m16n8k8.row.col.f32.tf32.tf32.f32 "
        "{%0,%1,%2,%3}, {%4,%5,%6,%7}, {%8,%9}, {%0,%1,%2,%3};"
        : "+f"(d[0]), "+f"(d[1]), "+f"(d[2]), "+f"(d[3])
        : "r"(a0), "r"(a1), "r"(a2), "r"(a3), "r"(b0), "r"(b1));
}

// N-dim permutation: GEMM col n holds physical i = phi(n),
//   phi(16k + 8h + 2m + u) = 16k + 4m + 2h + u; rho = phi^{-1}.
__device__ __forceinline__ int rho_row(int i) {
    return (i & 48) | (((i >> 1) & 1) << 3) | (((i >> 2) & 3) << 1) | (i & 1);
}

// Split B staging: batch the 4 LDG.128s (MLP=4), store later.
__device__ __forceinline__ void stage_B_ldg(float4* __restrict__ r,
                                            const float* __restrict__ Kb, int t) {
    #pragma unroll
    for (int it = 0; it < 4; ++it) {
        int idx = it * NTHREADS + t;       // 0..1023 float4 slots
        int i   = idx >> 4;                // physical K row 0..63
        int j4  = idx & 15;
        r[it] = *(const float4*)(Kb + (size_t)i * KER_ROW + j4 * 4);
    }
}
__device__ __forceinline__ void stage_B_sts(uint32_t* __restrict__ sB,
                                            const float4* __restrict__ r, int t) {
    #pragma unroll
    for (int it = 0; it < 4; ++it) {
        int idx = it * NTHREADS + t;
        int i   = idx >> 4;
        int j4  = idx & 15;
        uint4 w = { f2tf32(r[it].x), f2tf32(r[it].y), f2tf32(r[it].z), f2tf32(r[it].w) };
        *(uint4*)(sB + rho_row(i) * BSTR + j4 * 4) = w;
    }
}

__global__ void __launch_bounds__(NTHREADS, 2)
opn_mma_kernel(const float* __restrict__ emb, const float* __restrict__ ker,
               float* __restrict__ out)
{
    // smem (floats): sA raw 8704 | sB 4 x 4352 | sOut 1024  (108.5 KB)
    extern __shared__ __align__(16) uint32_t dynsmem[];
    uint32_t* sA   = dynsmem;
    uint32_t* sB   = dynsmem + A_FLOATS;
    float*    sOut = (float*)(sB + 4 * B_FLOATS);

    const int t    = threadIdx.x;
    const int w    = t >> 5;
    const int lane = t & 31;
    const int wp   = w & 1;     // pair within group
    const int ws   = w >> 1;    // batch strip: rows [ws*32, ws*32+32)
    const int m    = lane & 3;
    const int batch_base = blockIdx.x * BM;

    // ---- decode chunk id -> (r, first pair p0, #pairs np, first col c0) ----
    int cid = blockIdx.y, r = 0, pbase = 0;
    while (true) {
        int cnt = 31 - r;
        int nch = (cnt + PCHUNK - 1) >> 3;
        if (cid < nch) break;
        cid -= nch; pbase += cnt; ++r;
    }
    const int p0 = pbase + cid * PCHUNK;
    const int np = min(PCHUNK, (31 - r) - cid * PCHUNK);
    const int c0 = r + 1 + cid * PCHUNK;

    // ---- initial staging: batch all LDGs first (high MLP), then cvt+STS ----
    {
        const float* Pb = emb + (size_t)batch_base * EMB_ROW + (size_t)r * EMBED;
        float4 ra[8];
        #pragma unroll
        for (int it = 0; it < 8; ++it) {
            int idx = it * NTHREADS + t;   // 0..2047 float4 slots
            int b   = idx >> 4;
            int j4  = idx & 15;
            ra[it] = *(const float4*)(Pb + (size_t)b * EMB_ROW + j4 * 4);
        }
        float4 rb0[4], rb1[4];
        stage_B_ldg(rb0, ker + (size_t)p0 * EMBED, t);
        if (np > 1) stage_B_ldg(rb1, ker + (size_t)(p0 + 1) * EMBED, t);

        #pragma unroll
        for (int it = 0; it < 8; ++it) {
            int idx = it * NTHREADS + t;
            int b   = idx >> 4;
            int j4  = idx & 15;
            uint4 w_ = { f2tf32(ra[it].x), f2tf32(ra[it].y),
                         f2tf32(ra[it].z), f2tf32(ra[it].w) };
            *(uint4*)(sA + b * ASTR + j4 * 4) = w_;
        }
        stage_B_sts(sB, rb0, t);
        if (np > 1) stage_B_sts(sB + B_FLOATS, rb1, t);
    }
    __syncthreads();

    const int aBase = (ws * 32 + (lane >> 2)) * ASTR + m;
    const int bBase = (lane >> 2) * BSTR + m;

    const int ng = (np + 1) >> 1;
    for (int g = 0; g < ng; ++g) {
        const int cur = (g & 1) * 2;
        const int nxt = cur ^ 2;

        // ---- prefetch next group's B into REGISTERS (latency hidden by MMA) ----
        float4 pf0[4], pf1[4];
        bool have1 = false;
        const bool havePf = (g + 1 < ng);
        if (havePf) {
            int pi = 2 * (g + 1);
            stage_B_ldg(pf0, ker + (size_t)(p0 + pi) * EMBED, t);
            if (pi + 1 < np) {
                stage_B_ldg(pf1, ker + (size_t)(p0 + pi + 1) * EMBED, t);
                have1 = true;
            }
        }

        const int j = 2 * g + wp;          // pair slot within chunk
        float acc[2][8][4];
        if (j < np) {
            const uint32_t* Bp = sB + (cur + wp) * B_FLOATS + bBase;
            const uint32_t* Ap = sA + aBase;

            #pragma unroll
            for (int mm = 0; mm < 2; ++mm)
                #pragma unroll
                for (int nt = 0; nt < 8; ++nt)
                    #pragma unroll
                    for (int u = 0; u < 4; ++u)
                        acc[mm][nt][u] = 0.f;

            #pragma unroll
            for (int kt = 0; kt < 8; ++kt) {
                uint32_t a[2][4];
                #pragma unroll
                for (int mm = 0; mm < 2; ++mm) {
                    const uint32_t* Am = Ap + mm * 16 * ASTR + kt * 8;
                    a[mm][0] = Am[0];
                    a[mm][1] = Am[8 * ASTR];
                    a[mm][2] = Am[4];
                    a[mm][3] = Am[8 * ASTR + 4];
                }
                #pragma unroll
                for (int nt = 0; nt < 8; ++nt) {
                    const uint32_t* Bn = Bp + nt * 8 * BSTR + kt * 8;
                    uint32_t b0 = Bn[0];
                    uint32_t b1 = Bn[4];
                    mma_tf32(acc[0][nt], a[0][0], a[0][1], a[0][2], a[0][3], b0, b1);
                    mma_tf32(acc[1][nt], a[1][0], a[1][1], a[1][2], a[1][3], b0, b1);
                }
            }
        }

        // ---- drain prefetch: cvt + STS (pf regs die here, before epilogue) ----
        if (havePf) {
            stage_B_sts(sB + nxt * B_FLOATS, pf0, t);
            if (have1)
                stage_B_sts(sB + (nxt + 1) * B_FLOATS, pf1, t);
        }

        if (j < np) {
            // ---- epilogue: dense float4 q loads via the N permutation ----
            const int c = c0 + j;
            #pragma unroll
            for (int mm = 0; mm < 2; ++mm) {
                const int row0 = ws * 32 + mm * 16 + (lane >> 2);
                const float* q0 = emb + (size_t)(batch_base + row0) * EMB_ROW + (size_t)c * EMBED;
                const float* q1 = q0 + 8 * EMB_ROW;

                float s0 = 0.f, s1 = 0.f;
                #pragma unroll
                for (int k = 0; k < 4; ++k) {
                    float4 qv0 = *(const float4*)(q0 + k * 16 + m * 4);
                    float4 qv1 = *(const float4*)(q1 + k * 16 + m * 4);
                    s0 += qv0.x * acc[mm][2 * k][0] + qv0.y * acc[mm][2 * k][1]
                        + qv0.z * acc[mm][2 * k + 1][0] + qv0.w * acc[mm][2 * k + 1][1];
                    s1 += qv1.x * acc[mm][2 * k][2] + qv1.y * acc[mm][2 * k][3]
                        + qv1.z * acc[mm][2 * k + 1][2] + qv1.w * acc[mm][2 * k + 1][3];
                }
                s0 += __shfl_xor_sync(0xffffffffu, s0, 1);
                s0 += __shfl_xor_sync(0xffffffffu, s0, 2);
                s1 += __shfl_xor_sync(0xffffffffu, s1, 1);
                s1 += __shfl_xor_sync(0xffffffffu, s1, 2);

                if (m == 0) {
                    sOut[row0 * PCHUNK + j]       = s0;
                    sOut[(row0 + 8) * PCHUNK + j] = s1;
                }
            }
        }
        __syncthreads();   // B double-buffer + sOut ordering
    }

    // ---- coalesced output sweep ----
    #pragma unroll
    for (int u = 0; u < 4; ++u) {
        int idx = t * 4 + u;               // 0..1023
        int b = idx >> 3;
        int jj = idx & 7;
        if (jj < np)
            out[(size_t)(batch_base + b) * NPAIRS + p0 + jj] = sOut[idx];
    }
}

#define SMEM_TOTAL ((A_FLOATS + 4 * B_FLOATS + BM * PCHUNK) * 4)   // 108.5 KB

extern "C" void kernel_launch(void* const* d_in, const int* in_sizes, int n_in,
                              void* d_out, int out_size) {
    const float* emb = (const float*)d_in[0];   // (2048, 32, 64) f32
    const float* ker = (const float*)d_in[1];   // (64, 496, 64) f32
    float* out = (float*)d_out;                 // (2048, 1, 496) f32
    (void)in_sizes; (void)n_in; (void)out_size;

    static bool attr_set = false;
    if (!attr_set) {
        cudaFuncSetAttribute(opn_mma_kernel,
                             cudaFuncAttributeMaxDynamicSharedMemorySize, SMEM_TOTAL);
        attr_set = true;
    }
    dim3 grid(BATCH / BM, NCHUNKS);
    opn_mma_kernel<<<grid, NTHREADS, SMEM_TOTAL>>>(emb, ker, out);
}

// round 12
// speedup vs baseline: 1.3761x; 1.3761x over previous
#include <cuda_runtime.h>
#include <cuda_fp16.h>
#include <cstdint>

#define NFIELDS 32
#define EMBED   64
#define NPAIRS  496
#define BATCH   2048
#define EMB_ROW 2048                // halves per batch row (32*64)
#define KER_ROW 31744               // halves per i row (496*64)
#define EMB_N   (BATCH * NFIELDS * EMBED)   // 4194304
#define KER_N   (EMBED * NPAIRS * EMBED)    // 2031616

#define BM      128                 // batches per block
#define PCHUNK  8                   // pairs per block (all share one r)
#define NCHUNKS 76                  // sum over r of ceil((31-r)/8)
#define NTHREADS 256

#define ASTR 72                     // A row stride (halves): 144B -> banks 4r, conflict-free
#define BSTR 72                     // B row stride (halves)
#define A_HALVES (BM * ASTR)        // 9216
#define B_HALVES (EMBED * BSTR)     // 4608

// fp16 copies of the inputs (filled by conversion pre-pass)
__device__ __half g_emb_h[EMB_N];
__device__ __half g_ker_h[KER_N];

__global__ void conv_emb_kernel(const float* __restrict__ src) {
    int i = blockIdx.x * 256 + threadIdx.x;        // float4 slot
    float4 v = ((const float4*)src)[i];
    __half2 h0 = __floats2half2_rn(v.x, v.y);
    __half2 h1 = __floats2half2_rn(v.z, v.w);
    uint2 w;
    w.x = *reinterpret_cast<uint32_t*>(&h0);
    w.y = *reinterpret_cast<uint32_t*>(&h1);
    ((uint2*)g_emb_h)[i] = w;
}
__global__ void conv_ker_kernel(const float* __restrict__ src) {
    int i = blockIdx.x * 256 + threadIdx.x;
    float4 v = ((const float4*)src)[i];
    __half2 h0 = __floats2half2_rn(v.x, v.y);
    __half2 h1 = __floats2half2_rn(v.z, v.w);
    uint2 w;
    w.x = *reinterpret_cast<uint32_t*>(&h0);
    w.y = *reinterpret_cast<uint32_t*>(&h1);
    ((uint2*)g_ker_h)[i] = w;
}

__device__ __forceinline__ void mma_f16(float* d, uint32_t a0, uint32_t a1,
                                        uint32_t a2, uint32_t a3,
                                        uint32_t b0, uint32_t b1) {
    asm("mma.sync.aligned.m16n8k16.row.col.f32.f16.f16.f32 "
        "{%0,%1,%2,%3}, {%4,%5,%6,%7}, {%8,%9}, {%0,%1,%2,%3};"
        : "+f"(d[0]), "+f"(d[1]), "+f"(d[2]), "+f"(d[3])
        : "r"(a0), "r"(a1), "r"(a2), "r"(a3), "r"(b0), "r"(b1));
}

// N-dim permutation: GEMM col n holds physical i = phi(n),
//   phi(16T + 8h + 2m + u) = 16T + 4m + 2h + u; rho = phi^{-1}.
__device__ __forceinline__ int rho_row(int i) {
    return (i & 48) | (((i >> 1) & 1) << 3) | (((i >> 2) & 3) << 1) | (i & 1);
}

// Dense f16 stage of K_p (64x64) -> smem [rho(i)*BSTR + j] (pure uint4 copies)
__device__ __forceinline__ void stage_B(__half* __restrict__ sB,
                                        const __half* __restrict__ Kb, int t) {
    #pragma unroll
    for (int it = 0; it < 2; ++it) {
        int idx = it * NTHREADS + t;       // 0..511 uint4 slots (8 halves each)
        int i   = idx >> 3;                // physical K row 0..63
        int j8  = idx & 7;
        *(uint4*)(sB + rho_row(i) * BSTR + j8 * 8) =
            *(const uint4*)(Kb + (size_t)i * KER_ROW + j8 * 8);
    }
}

__global__ void __launch_bounds__(NTHREADS, 2)
opn_mma_kernel(float* __restrict__ out)
{
    // smem (halves): sA 9216 | sB 4 x 4608 | sOut 1024 f32  (59392 B)
    extern __shared__ __align__(16) __half dynsmem[];
    __half* sA   = dynsmem;
    __half* sB   = dynsmem + A_HALVES;
    float*  sOut = (float*)(sB + 4 * B_HALVES);

    const int t    = threadIdx.x;
    const int w    = t >> 5;
    const int lane = t & 31;
    const int wp   = w & 1;     // pair within group
    const int ws   = w >> 1;    // batch strip: rows [ws*32, ws*32+32)
    const int m    = lane & 3;
    const int batch_base = blockIdx.x * BM;

    // ---- decode chunk id -> (r, first pair p0, #pairs np, first col c0) ----
    int cid = blockIdx.y, r = 0, pbase = 0;
    while (true) {
        int cnt = 31 - r;
        int nch = (cnt + PCHUNK - 1) >> 3;
        if (cid < nch) break;
        cid -= nch; pbase += cnt; ++r;
    }
    const int p0 = pbase + cid * PCHUNK;
    const int np = min(PCHUNK, (31 - r) - cid * PCHUNK);
    const int c0 = r + 1 + cid * PCHUNK;

    // ---- stage A: sA[b*ASTR + j] = emb_h[batch_base+b, r, j] (uint4 copies) ----
    {
        const __half* Pb = g_emb_h + (size_t)batch_base * EMB_ROW + r * EMBED;
        #pragma unroll
        for (int it = 0; it < 4; ++it) {
            int idx = it * NTHREADS + t;   // 0..1023 uint4 slots
            int b   = idx >> 3;            // 0..127
            int j8  = idx & 7;
            *(uint4*)(sA + b * ASTR + j8 * 8) =
                *(const uint4*)(Pb + (size_t)b * EMB_ROW + j8 * 8);
        }
    }
    stage_B(sB, g_ker_h + p0 * EMBED, t);
    if (np > 1) stage_B(sB + B_HALVES, g_ker_h + (p0 + 1) * EMBED, t);
    __syncthreads();

    const __half* Ap = sA + (ws * 32 + (lane >> 2)) * ASTR + 2 * m;
    const int bOff = (lane >> 2) * BSTR + 2 * m;

    const int ng = (np + 1) >> 1;
    for (int g = 0; g < ng; ++g) {
        const int cur = (g & 1) * 2;
        const int nxt = cur ^ 2;

        // prefetch next group's B into smem (pure copies, overlaps MMA+epilogue)
        if (g + 1 < ng) {
            int pi = 2 * (g + 1);
            stage_B(sB + nxt * B_HALVES, g_ker_h + (p0 + pi) * EMBED, t);
            if (pi + 1 < np)
                stage_B(sB + (nxt + 1) * B_HALVES, g_ker_h + (p0 + pi + 1) * EMBED, t);
        }

        const int j = 2 * g + wp;          // pair slot within chunk
        if (j < np) {
            const __half* Bp = sB + (cur + wp) * B_HALVES + bOff;

            float acc[2][8][4];
            #pragma unroll
            for (int mm = 0; mm < 2; ++mm)
                #pragma unroll
                for (int nt = 0; nt < 8; ++nt)
                    #pragma unroll
                    for (int u = 0; u < 4; ++u)
                        acc[mm][nt][u] = 0.f;

            #pragma unroll
            for (int kt = 0; kt < 4; ++kt) {       // K = 4 x 16
                uint32_t a[2][4];
                #pragma unroll
                for (int mm = 0; mm < 2; ++mm) {
                    const __half* Am = Ap + mm * 16 * ASTR + kt * 16;
                    a[mm][0] = *(const uint32_t*)(Am);
                    a[mm][1] = *(const uint32_t*)(Am + 8 * ASTR);
                    a[mm][2] = *(const uint32_t*)(Am + 8);
                    a[mm][3] = *(const uint32_t*)(Am + 8 * ASTR + 8);
                }
                #pragma unroll
                for (int nt = 0; nt < 8; ++nt) {
                    const __half* Bn = Bp + nt * 8 * BSTR + kt * 16;
                    uint32_t b0 = *(const uint32_t*)(Bn);
                    uint32_t b1 = *(const uint32_t*)(Bn + 8);
                    mma_f16(acc[0][nt], a[0][0], a[0][1], a[0][2], a[0][3], b0, b1);
                    mma_f16(acc[1][nt], a[1][0], a[1][1], a[1][2], a[1][3], b0, b1);
                }
            }

            // ---- epilogue: f16 q loads (dense via N permutation) ----
            // acc[mm][2T+h][2v+u] pairs with q[row_v][16T + 4m + 2h + u]
            const int c = c0 + j;
            #pragma unroll
            for (int mm = 0; mm < 2; ++mm) {
                const int row0 = ws * 32 + mm * 16 + (lane >> 2);
                const __half* q0 = g_emb_h + (size_t)(batch_base + row0) * EMB_ROW
                                 + c * EMBED + m * 4;
                const __half* q1 = q0 + 8 * EMB_ROW;

                float s0 = 0.f, s1 = 0.f;
                #pragma unroll
                for (int T = 0; T < 4; ++T) {
                    uint2 r0 = *(const uint2*)(q0 + T * 16);
                    uint2 r1 = *(const uint2*)(q1 + T * 16);
                    float2 f00 = __half22float2(*reinterpret_cast<__half2*>(&r0.x));
                    float2 f01 = __half22float2(*reinterpret_cast<__half2*>(&r0.y));
                    float2 f10 = __half22float2(*reinterpret_cast<__half2*>(&r1.x));
                    float2 f11 = __half22float2(*reinterpret_cast<__half2*>(&r1.y));
                    s0 += f00.x * acc[mm][2 * T][0] + f00.y * acc[mm][2 * T][1]
                        + f01.x * acc[mm][2 * T + 1][0] + f01.y * acc[mm][2 * T + 1][1];
                    s1 += f10.x * acc[mm][2 * T][2] + f10.y * acc[mm][2 * T][3]
                        + f11.x * acc[mm][2 * T + 1][2] + f11.y * acc[mm][2 * T + 1][3];
                }
                s0 += __shfl_xor_sync(0xffffffffu, s0, 1);
                s0 += __shfl_xor_sync(0xffffffffu, s0, 2);
                s1 += __shfl_xor_sync(0xffffffffu, s1, 1);
                s1 += __shfl_xor_sync(0xffffffffu, s1, 2);

                if (m == 0) {
                    sOut[row0 * PCHUNK + j]       = s0;
                    sOut[(row0 + 8) * PCHUNK + j] = s1;
                }
            }
        }
        __syncthreads();   // B double-buffer + sOut ordering
    }

    // ---- coalesced output sweep ----
    #pragma unroll
    for (int u = 0; u < 4; ++u) {
        int idx = t * 4 + u;               // 0..1023
        int b = idx >> 3;
        int jj = idx & 7;
        if (jj < np)
            out[(size_t)(batch_base + b) * NPAIRS + p0 + jj] = sOut[idx];
    }
}

#define SMEM_TOTAL (A_HALVES * 2 + 4 * B_HALVES * 2 + BM * PCHUNK * 4)   // 59392 B

extern "C" void kernel_launch(void* const* d_in, const int* in_sizes, int n_in,
                              void* d_out, int out_size) {
    const float* emb = (const float*)d_in[0];   // (2048, 32, 64) f32
    const float* ker = (const float*)d_in[1];   // (64, 496, 64) f32
    float* out = (float*)d_out;                 // (2048, 1, 496) f32
    (void)in_sizes; (void)n_in; (void)out_size;

    static bool attr_set = false;
    if (!attr_set) {
        cudaFuncSetAttribute(opn_mma_kernel,
                             cudaFuncAttributeMaxDynamicSharedMemorySize, SMEM_TOTAL);
        attr_set = true;
    }
    conv_emb_kernel<<<EMB_N / 4 / 256, 256>>>(emb);   // 4096 blocks
    conv_ker_kernel<<<KER_N / 4 / 256, 256>>>(ker);   // 1984 blocks
    dim3 grid(BATCH / BM, NCHUNKS);
    opn_mma_kernel<<<grid, NTHREADS, SMEM_TOTAL>>>(out);
}

// round 13
// speedup vs baseline: 1.4748x; 1.0717x over previous
#include <cuda_runtime.h>
#include <cuda_fp16.h>
#include <cstdint>

#define NFIELDS 32
#define EMBED   64
#define NPAIRS  496
#define BATCH   2048
#define EMB_ROW 2048                // halves per batch row (32*64)
#define KER_ROW 31744               // halves per i row (496*64)
#define EMB_N   (BATCH * NFIELDS * EMBED)   // 4194304
#define KER_N   (EMBED * NPAIRS * EMBED)    // 2031616
#define EMB_SLOTS (EMB_N / 4)               // 1048576 float4 slots
#define KER_SLOTS (KER_N / 4)               // 507904

#define BM      128                 // batches per block
#define PCHUNK  8                   // pairs per block (all share one r)
#define NCHUNKS 76                  // sum over r of ceil((31-r)/8)
#define NTHREADS 256

#define ASTR 72                     // A row stride (halves): conflict-free
#define BSTR 72                     // B row stride (halves)
#define A_HALVES (BM * ASTR)        // 9216
#define B_HALVES (EMBED * BSTR)     // 4608

// fp16 copies of the inputs (filled by conversion pre-pass)
__device__ __half g_emb_h[EMB_N];
__device__ __half g_ker_h[KER_N];

__global__ void conv_kernel(const float* __restrict__ emb,
                            const float* __restrict__ ker) {
    int i = blockIdx.x * 256 + threadIdx.x;        // global float4 slot
    const float4* src;
    uint2* dst;
    int k;
    if (i < EMB_SLOTS) {
        src = (const float4*)emb; dst = (uint2*)g_emb_h; k = i;
    } else {
        src = (const float4*)ker; dst = (uint2*)g_ker_h; k = i - EMB_SLOTS;
    }
    float4 v = src[k];
    __half2 h0 = __floats2half2_rn(v.x, v.y);
    __half2 h1 = __floats2half2_rn(v.z, v.w);
    uint2 w;
    w.x = *reinterpret_cast<uint32_t*>(&h0);
    w.y = *reinterpret_cast<uint32_t*>(&h1);
    dst[k] = w;
}

__device__ __forceinline__ void mma_f16(float* d, uint32_t a0, uint32_t a1,
                                        uint32_t a2, uint32_t a3,
                                        uint32_t b0, uint32_t b1) {
    asm("mma.sync.aligned.m16n8k16.row.col.f32.f16.f16.f32 "
        "{%0,%1,%2,%3}, {%4,%5,%6,%7}, {%8,%9}, {%0,%1,%2,%3};"
        : "+f"(d[0]), "+f"(d[1]), "+f"(d[2]), "+f"(d[3])
        : "r"(a0), "r"(a1), "r"(a2), "r"(a3), "r"(b0), "r"(b1));
}

// N-dim permutation: GEMM col n holds physical i = phi(n),
//   phi(16T + 8h + 2m + u) = 16T + 4m + 2h + u; rho = phi^{-1}.
__device__ __forceinline__ int rho_row(int i) {
    return (i & 48) | (((i >> 1) & 1) << 3) | (((i >> 2) & 3) << 1) | (i & 1);
}

__global__ void __launch_bounds__(NTHREADS, 2)
opn_mma_kernel(float* __restrict__ out)
{
    // smem (bytes): sA 18432 | sB 8 x 9216 | sOut 4096  -> 96256 B
    extern __shared__ __align__(16) __half dynsmem[];
    __half* sA   = dynsmem;
    __half* sB   = dynsmem + A_HALVES;
    float*  sOut = (float*)(sB + PCHUNK * B_HALVES);

    const int t    = threadIdx.x;
    const int w    = t >> 5;
    const int lane = t & 31;
    const int wp   = w & 1;     // pair parity: this warp handles pairs wp, wp+2, ...
    const int ws   = w >> 1;    // batch strip: rows [ws*32, ws*32+32)
    const int m    = lane & 3;
    const int batch_base = blockIdx.x * BM;

    // ---- decode chunk id -> (r, first pair p0, #pairs np, first col c0) ----
    int cid = blockIdx.y, r = 0, pbase = 0;
    while (true) {
        int cnt = 31 - r;
        int nch = (cnt + PCHUNK - 1) >> 3;
        if (cid < nch) break;
        cid -= nch; pbase += cnt; ++r;
    }
    const int p0 = pbase + cid * PCHUNK;
    const int np = min(PCHUNK, (31 - r) - cid * PCHUNK);
    const int c0 = r + 1 + cid * PCHUNK;

    // ---- stage A: sA[b*ASTR + j] = emb_h[batch_base+b, r, j] ----
    {
        const __half* Pb = g_emb_h + (size_t)batch_base * EMB_ROW + r * EMBED;
        #pragma unroll
        for (int it = 0; it < 4; ++it) {
            int idx = it * NTHREADS + t;   // 0..1023 uint4 slots
            int b   = idx >> 3;            // 0..127
            int j8  = idx & 7;
            *(uint4*)(sA + b * ASTR + j8 * 8) =
                *(const uint4*)(Pb + (size_t)b * EMB_ROW + j8 * 8);
        }
    }
    // ---- stage ALL pairs' B tiles (one shot, high MLP) ----
    {
        #pragma unroll
        for (int it = 0; it < 16; ++it) {
            int idx  = it * NTHREADS + t;  // 0..4095
            int pair = idx >> 9;           // 0..7
            int slot = idx & 511;
            if (pair < np) {
                int i  = slot >> 3;        // physical K row 0..63
                int j8 = slot & 7;
                *(uint4*)(sB + pair * B_HALVES + rho_row(i) * BSTR + j8 * 8) =
                    *(const uint4*)(g_ker_h + (size_t)(p0 + pair) * EMBED
                                    + (size_t)i * KER_ROW + j8 * 8);
            }
        }
    }
    __syncthreads();   // the ONLY barrier before the output sweep

    // ---- hoist A fragments into registers (shared across all 4 pairs) ----
    const __half* Ap = sA + (ws * 32 + (lane >> 2)) * ASTR + 2 * m;
    uint32_t a[4][2][4];
    #pragma unroll
    for (int kt = 0; kt < 4; ++kt)
        #pragma unroll
        for (int mm = 0; mm < 2; ++mm) {
            const __half* Am = Ap + mm * 16 * ASTR + kt * 16;
            a[kt][mm][0] = *(const uint32_t*)(Am);
            a[kt][mm][1] = *(const uint32_t*)(Am + 8 * ASTR);
            a[kt][mm][2] = *(const uint32_t*)(Am + 8);
            a[kt][mm][3] = *(const uint32_t*)(Am + 8 * ASTR + 8);
        }

    const int bOff = (lane >> 2) * BSTR + 2 * m;

    // ---- barrier-free pair loop: each warp owns pairs wp, wp+2, wp+4, wp+6 ----
    #pragma unroll 1
    for (int g = 0; g < 4; ++g) {
        const int j = 2 * g + wp;
        if (j >= np) continue;
        const __half* Bp = sB + j * B_HALVES + bOff;

        float acc[2][8][4];
        #pragma unroll
        for (int mm = 0; mm < 2; ++mm)
            #pragma unroll
            for (int nt = 0; nt < 8; ++nt)
                #pragma unroll
                for (int u = 0; u < 4; ++u)
                    acc[mm][nt][u] = 0.f;

        #pragma unroll
        for (int kt = 0; kt < 4; ++kt) {
            #pragma unroll
            for (int nt = 0; nt < 8; ++nt) {
                const __half* Bn = Bp + nt * 8 * BSTR + kt * 16;
                uint32_t b0 = *(const uint32_t*)(Bn);
                uint32_t b1 = *(const uint32_t*)(Bn + 8);
                mma_f16(acc[0][nt], a[kt][0][0], a[kt][0][1], a[kt][0][2], a[kt][0][3], b0, b1);
                mma_f16(acc[1][nt], a[kt][1][0], a[kt][1][1], a[kt][1][2], a[kt][1][3], b0, b1);
            }
        }

        // ---- epilogue: f16 q loads (dense via N permutation) ----
        const int c = c0 + j;
        #pragma unroll
        for (int mm = 0; mm < 2; ++mm) {
            const int row0 = ws * 32 + mm * 16 + (lane >> 2);
            const __half* q0 = g_emb_h + (size_t)(batch_base + row0) * EMB_ROW
                             + c * EMBED + m * 4;
            const __half* q1 = q0 + 8 * EMB_ROW;

            float s0 = 0.f, s1 = 0.f;
            #pragma unroll
            for (int T = 0; T < 4; ++T) {
                uint2 r0 = *(const uint2*)(q0 + T * 16);
                uint2 r1 = *(const uint2*)(q1 + T * 16);
                float2 f00 = __half22float2(*reinterpret_cast<__half2*>(&r0.x));
                float2 f01 = __half22float2(*reinterpret_cast<__half2*>(&r0.y));
                float2 f10 = __half22float2(*reinterpret_cast<__half2*>(&r1.x));
                float2 f11 = __half22float2(*reinterpret_cast<__half2*>(&r1.y));
                s0 += f00.x * acc[mm][2 * T][0] + f00.y * acc[mm][2 * T][1]
                    + f01.x * acc[mm][2 * T + 1][0] + f01.y * acc[mm][2 * T + 1][1];
                s1 += f10.x * acc[mm][2 * T][2] + f10.y * acc[mm][2 * T][3]
                    + f11.x * acc[mm][2 * T + 1][2] + f11.y * acc[mm][2 * T + 1][3];
            }
            s0 += __shfl_xor_sync(0xffffffffu, s0, 1);
            s0 += __shfl_xor_sync(0xffffffffu, s0, 2);
            s1 += __shfl_xor_sync(0xffffffffu, s1, 1);
            s1 += __shfl_xor_sync(0xffffffffu, s1, 2);

            if (m == 0) {
                sOut[row0 * PCHUNK + j]       = s0;
                sOut[(row0 + 8) * PCHUNK + j] = s1;
            }
        }
    }
    __syncthreads();

    // ---- coalesced output sweep ----
    #pragma unroll
    for (int u = 0; u < 4; ++u) {
        int idx = t * 4 + u;               // 0..1023
        int b = idx >> 3;
        int jj = idx & 7;
        if (jj < np)
            out[(size_t)(batch_base + b) * NPAIRS + p0 + jj] = sOut[idx];
    }
}

#define SMEM_TOTAL (A_HALVES * 2 + PCHUNK * B_HALVES * 2 + BM * PCHUNK * 4)  // 96256 B

extern "C" void kernel_launch(void* const* d_in, const int* in_sizes, int n_in,
                              void* d_out, int out_size) {
    const float* emb = (const float*)d_in[0];   // (2048, 32, 64) f32
    const float* ker = (const float*)d_in[1];   // (64, 496, 64) f32
    float* out = (float*)d_out;                 // (2048, 1, 496) f32
    (void)in_sizes; (void)n_in; (void)out_size;

    static bool attr_set = false;
    if (!attr_set) {
        cudaFuncSetAttribute(opn_mma_kernel,
                             cudaFuncAttributeMaxDynamicSharedMemorySize, SMEM_TOTAL);
        attr_set = true;
    }
    conv_kernel<<<(EMB_SLOTS + KER_SLOTS) / 256, 256>>>(emb, ker);  // 6080 blocks
    dim3 grid(BATCH / BM, NCHUNKS);
    opn_mma_kernel<<<grid, NTHREADS, SMEM_TOTAL>>>(out);
}

// round 14
// speedup vs baseline: 1.6041x; 1.0877x over previous
#include <cuda_runtime.h>
#include <cuda_fp16.h>
#include <cstdint>

#define NFIELDS 32
#define EMBED   64
#define NPAIRS  496
#define BATCH   2048
#define EMB_ROW 2048                // halves per batch row (32*64)
#define KER_ROW 31744               // halves per i row (496*64)
#define EMB_N   (BATCH * NFIELDS * EMBED)   // 4194304
#define KER_N   (EMBED * NPAIRS * EMBED)    // 2031616
#define EMB_SLOTS (EMB_N / 4)               // float4 slots
#define KER_SLOTS (KER_N / 4)

#define BM      128                 // batches per block
#define PCHUNK  8                   // pairs per block (all share one r)
#define NCHUNKS 76                  // sum over r of ceil((31-r)/8)
#define NTHREADS 256

#define ASTR 72                     // A row stride (halves): conflict-free
#define BSTR 72                     // B row stride (halves)
#define A_HALVES (BM * ASTR)        // 9216
#define B_HALVES (EMBED * BSTR)     // 4608

// fp16 copies of the inputs (filled by conversion pre-pass)
__device__ __half g_emb_h[EMB_N];
__device__ __half g_ker_h[KER_N];

__global__ void conv_kernel(const float* __restrict__ emb,
                            const float* __restrict__ ker) {
    int i = blockIdx.x * 256 + threadIdx.x;        // global float4 slot
    const float4* src;
    uint2* dst;
    int k;
    if (i < EMB_SLOTS) {
        src = (const float4*)emb; dst = (uint2*)g_emb_h; k = i;
    } else {
        src = (const float4*)ker; dst = (uint2*)g_ker_h; k = i - EMB_SLOTS;
    }
    float4 v = src[k];
    __half2 h0 = __floats2half2_rn(v.x, v.y);
    __half2 h1 = __floats2half2_rn(v.z, v.w);
    uint2 w;
    w.x = *reinterpret_cast<uint32_t*>(&h0);
    w.y = *reinterpret_cast<uint32_t*>(&h1);
    dst[k] = w;
}

__device__ __forceinline__ void mma_f16(float* d, uint32_t a0, uint32_t a1,
                                        uint32_t a2, uint32_t a3,
                                        uint32_t b0, uint32_t b1) {
    asm("mma.sync.aligned.m16n8k16.row.col.f32.f16.f16.f32 "
        "{%0,%1,%2,%3}, {%4,%5,%6,%7}, {%8,%9}, {%0,%1,%2,%3};"
        : "+f"(d[0]), "+f"(d[1]), "+f"(d[2]), "+f"(d[3])
        : "r"(a0), "r"(a1), "r"(a2), "r"(a3), "r"(b0), "r"(b1));
}

// N-dim permutation (chosen for dense q loads):
//   GEMM col n = 16T + 8h + 2m + u holds physical i = phi(n) = 16m + 4T + 2h + u.
// Staging stores physical row i at smem row rho(i) = phi^{-1}(i):
//   i bits: u=i[0], h=i[1], T=i[2:4], m=i[4:6] ->  n = 16T + 8h + 2m + u.
__device__ __forceinline__ int rho_row(int i) {
    return (((i >> 2) & 3) << 4) | (((i >> 1) & 1) << 3) | (((i >> 4) & 3) << 1) | (i & 1);
}

__global__ void __launch_bounds__(NTHREADS, 2)
opn_mma_kernel(float* __restrict__ out)
{
    // smem (bytes): sA 18432 | sB 8 x 9216 | sOut 4096  -> 96256 B
    extern __shared__ __align__(16) __half dynsmem[];
    __half* sA   = dynsmem;
    __half* sB   = dynsmem + A_HALVES;
    float*  sOut = (float*)(sB + PCHUNK * B_HALVES);

    const int t    = threadIdx.x;
    const int w    = t >> 5;
    const int lane = t & 31;
    const int wp   = w & 1;     // pair parity: this warp handles pairs wp, wp+2, ...
    const int ws   = w >> 1;    // batch strip: rows [ws*32, ws*32+32)
    const int m    = lane & 3;
    const int batch_base = blockIdx.x * BM;

    // ---- decode chunk id -> (r, first pair p0, #pairs np, first col c0) ----
    int cid = blockIdx.y, r = 0, pbase = 0;
    while (true) {
        int cnt = 31 - r;
        int nch = (cnt + PCHUNK - 1) >> 3;
        if (cid < nch) break;
        cid -= nch; pbase += cnt; ++r;
    }
    const int p0 = pbase + cid * PCHUNK;
    const int np = min(PCHUNK, (31 - r) - cid * PCHUNK);
    const int c0 = r + 1 + cid * PCHUNK;

    // ---- stage A: sA[b*ASTR + j] = emb_h[batch_base+b, r, j] ----
    {
        const __half* Pb = g_emb_h + (size_t)batch_base * EMB_ROW + r * EMBED;
        #pragma unroll
        for (int it = 0; it < 4; ++it) {
            int idx = it * NTHREADS + t;   // 0..1023 uint4 slots
            int b   = idx >> 3;            // 0..127
            int j8  = idx & 7;
            *(uint4*)(sA + b * ASTR + j8 * 8) =
                *(const uint4*)(Pb + (size_t)b * EMB_ROW + j8 * 8);
        }
    }
    // ---- stage ALL pairs' B tiles (one shot, high MLP) ----
    {
        #pragma unroll
        for (int it = 0; it < 16; ++it) {
            int idx  = it * NTHREADS + t;  // 0..4095
            int pair = idx >> 9;           // 0..7
            int slot = idx & 511;
            if (pair < np) {
                int i  = slot >> 3;        // physical K row 0..63
                int j8 = slot & 7;
                *(uint4*)(sB + pair * B_HALVES + rho_row(i) * BSTR + j8 * 8) =
                    *(const uint4*)(g_ker_h + (size_t)(p0 + pair) * EMBED
                                    + (size_t)i * KER_ROW + j8 * 8);
            }
        }
    }
    __syncthreads();   // the ONLY barrier before the output sweep

    // ---- hoist A fragments into registers (shared across all 4 pairs) ----
    const __half* Ap = sA + (ws * 32 + (lane >> 2)) * ASTR + 2 * m;
    uint32_t a[4][2][4];
    #pragma unroll
    for (int kt = 0; kt < 4; ++kt)
        #pragma unroll
        for (int mm = 0; mm < 2; ++mm) {
            const __half* Am = Ap + mm * 16 * ASTR + kt * 16;
            a[kt][mm][0] = *(const uint32_t*)(Am);
            a[kt][mm][1] = *(const uint32_t*)(Am + 8 * ASTR);
            a[kt][mm][2] = *(const uint32_t*)(Am + 8);
            a[kt][mm][3] = *(const uint32_t*)(Am + 8 * ASTR + 8);
        }

    const int bOff = (lane >> 2) * BSTR + 2 * m;

    // ---- barrier-free pair loop ----
    #pragma unroll 1
    for (int g = 0; g < 4; ++g) {
        const int j = 2 * g + wp;
        if (j >= np) continue;
        const __half* Bp = sB + j * B_HALVES + bOff;

        float acc[2][8][4];
        #pragma unroll
        for (int mm = 0; mm < 2; ++mm)
            #pragma unroll
            for (int nt = 0; nt < 8; ++nt)
                #pragma unroll
                for (int u = 0; u < 4; ++u)
                    acc[mm][nt][u] = 0.f;

        #pragma unroll
        for (int kt = 0; kt < 4; ++kt) {
            #pragma unroll
            for (int nt = 0; nt < 8; ++nt) {
                const __half* Bn = Bp + nt * 8 * BSTR + kt * 16;
                uint32_t b0 = *(const uint32_t*)(Bn);
                uint32_t b1 = *(const uint32_t*)(Bn + 8);
                mma_f16(acc[0][nt], a[kt][0][0], a[kt][0][1], a[kt][0][2], a[kt][0][3], b0, b1);
                mma_f16(acc[1][nt], a[kt][1][0], a[kt][1][1], a[kt][1][2], a[kt][1][3], b0, b1);
            }
        }

        // ---- epilogue: DENSE q loads. Lane m needs phys cols [16m, 16m+16):
        //   uint4 lo = halves 16m+0..7  (nt = 0..3, packed half2 per nt)
        //   uint4 hi = halves 16m+8..15 (nt = 4..7)
        //   word p of lo/hi = (q[nt=inst*4+p][u=0], q[..][u=1])
        const int c = c0 + j;
        #pragma unroll
        for (int mm = 0; mm < 2; ++mm) {
            const int row0 = ws * 32 + mm * 16 + (lane >> 2);
            const __half* q0 = g_emb_h + (size_t)(batch_base + row0) * EMB_ROW
                             + c * EMBED + m * 16;
            const __half* q1 = q0 + 8 * EMB_ROW;

            uint4 lo0 = *(const uint4*)(q0);
            uint4 hi0 = *(const uint4*)(q0 + 8);
            uint4 lo1 = *(const uint4*)(q1);
            uint4 hi1 = *(const uint4*)(q1 + 8);

            float s0 = 0.f, s1 = 0.f;
            const uint32_t* w0[2] = { &lo0.x, &hi0.x };
            const uint32_t* w1[2] = { &lo1.x, &hi1.x };
            #pragma unroll
            for (int inst = 0; inst < 2; ++inst)
                #pragma unroll
                for (int p = 0; p < 4; ++p) {
                    float2 f0 = __half22float2(*reinterpret_cast<const __half2*>(&w0[inst][p]));
                    float2 f1 = __half22float2(*reinterpret_cast<const __half2*>(&w1[inst][p]));
                    const int nt = inst * 4 + p;
                    s0 += f0.x * acc[mm][nt][0] + f0.y * acc[mm][nt][1];
                    s1 += f1.x * acc[mm][nt][2] + f1.y * acc[mm][nt][3];
                }
            s0 += __shfl_xor_sync(0xffffffffu, s0, 1);
            s0 += __shfl_xor_sync(0xffffffffu, s0, 2);
            s1 += __shfl_xor_sync(0xffffffffu, s1, 1);
            s1 += __shfl_xor_sync(0xffffffffu, s1, 2);

            if (m == 0) {
                sOut[row0 * PCHUNK + j]       = s0;
                sOut[(row0 + 8) * PCHUNK + j] = s1;
            }
        }
    }
    __syncthreads();

    // ---- coalesced output sweep ----
    #pragma unroll
    for (int u = 0; u < 4; ++u) {
        int idx = t * 4 + u;               // 0..1023
        int b = idx >> 3;
        int jj = idx & 7;
        if (jj < np)
            out[(size_t)(batch_base + b) * NPAIRS + p0 + jj] = sOut[idx];
    }
}

#define SMEM_TOTAL (A_HALVES * 2 + PCHUNK * B_HALVES * 2 + BM * PCHUNK * 4)  // 96256 B

extern "C" void kernel_launch(void* const* d_in, const int* in_sizes, int n_in,
                              void* d_out, int out_size) {
    const float* emb = (const float*)d_in[0];   // (2048, 32, 64) f32
    const float* ker = (const float*)d_in[1];   // (64, 496, 64) f32
    float* out = (float*)d_out;                 // (2048, 1, 496) f32
    (void)in_sizes; (void)n_in; (void)out_size;

    static bool attr_set = false;
    if (!attr_set) {
        cudaFuncSetAttribute(opn_mma_kernel,
                             cudaFuncAttributeMaxDynamicSharedMemorySize, SMEM_TOTAL);
        attr_set = true;
    }
    conv_kernel<<<(EMB_SLOTS + KER_SLOTS) / 256, 256>>>(emb, ker);
    dim3 grid(BATCH / BM, NCHUNKS);
    opn_mma_kernel<<<grid, NTHREADS, SMEM_TOTAL>>>(out);
}